// round 1
// baseline (speedup 1.0000x reference)
#include <cuda_runtime.h>
#include <math.h>

#define NPTS 512
#define DCLS 9
#define LLAT 32

__device__ __forceinline__ float warpReduceSum(float v) {
    #pragma unroll
    for (int o = 16; o > 0; o >>= 1)
        v += __shfl_down_sync(0xFFFFFFFFu, v, o);
    return v;
}

__global__ __launch_bounds__(NPTS) void loss_kernel(
    const float* __restrict__ kine_input,   // [B, N, 4]
    const float* __restrict__ class_input,  // [B, N, 9]
    const float* __restrict__ kine_pred,    // [B, N, 4]
    const float* __restrict__ class_pred,   // [B, N, 9]
    const float* __restrict__ mu,           // [B, 32]
    const float* __restrict__ log_var,      // [B, 32]
    float* __restrict__ out)                // [B]
{
    const int b = blockIdx.x;
    const int t = threadIdx.x;

    __shared__ float4 sx[NPTS];
    __shared__ float4 sy[NPTS];
    __shared__ float  sx2[NPTS];
    __shared__ float  sy2[NPTS];
    __shared__ int    hin[DCLS];
    __shared__ int    hpred[DCLS];
    __shared__ float  red[16];

    if (t < DCLS) { hin[t] = 0; hpred[t] = 0; }

    // ---- stage kine points + squared norms into smem ----
    const float4 x = reinterpret_cast<const float4*>(kine_input)[b * NPTS + t];
    const float myx2 = x.x * x.x + x.y * x.y + x.z * x.z + x.w * x.w;
    sx[t] = x; sx2[t] = myx2;

    const float4 y = reinterpret_cast<const float4*>(kine_pred)[b * NPTS + t];
    const float myy2 = y.x * y.x + y.y * y.y + y.z * y.z + y.w * y.w;
    sy[t] = y; sy2[t] = myy2;

    // ---- class rows into registers; compute labels (first-max index) ----
    float ci[DCLS], cp[DCLS];
    {
        const float* cip = class_input + ((size_t)b * NPTS + t) * DCLS;
        const float* cpp = class_pred  + ((size_t)b * NPTS + t) * DCLS;
        #pragma unroll
        for (int d = 0; d < DCLS; d++) { ci[d] = cip[d]; cp[d] = cpp[d]; }
    }
    int li = 0, lp = 0;
    {
        float mi = ci[0], mp = cp[0];
        #pragma unroll
        for (int d = 1; d < DCLS; d++) {
            if (ci[d] > mi) { mi = ci[d]; li = d; }
            if (cp[d] > mp) { mp = cp[d]; lp = d; }
        }
    }

    __syncthreads();   // smem points ready; hist init done

    atomicAdd(&hin[li], 1);
    atomicAdd(&hpred[lp], 1);

    // ---- pass 1: for my input point, min over all pred points ----
    float bd1 = 3.4e38f; int bi1 = 0;
    #pragma unroll 4
    for (int m = 0; m < NPTS; m++) {
        float4 yy = sy[m];
        float dot = x.x * yy.x + x.y * yy.y + x.z * yy.z + x.w * yy.w;
        float dv  = fmaxf(fmaf(-2.0f, dot, myx2 + sy2[m]), 0.0f);
        if (dv < bd1) { bd1 = dv; bi1 = m; }
    }

    // ---- pass 2: for my pred point, min over all input points ----
    float bd2 = 3.4e38f; int bi2 = 0;
    #pragma unroll 4
    for (int n = 0; n < NPTS; n++) {
        float4 xx = sx[n];
        float dot = y.x * xx.x + y.y * xx.y + y.z * xx.z + y.w * xx.w;
        float dv  = fmaxf(fmaf(-2.0f, dot, myy2 + sx2[n]), 0.0f);
        if (dv < bd2) { bd2 = dv; bi2 = n; }
    }

    // ---- classification gathers ----
    float s1 = 0.0f, s2 = 0.0f;
    {
        const float* gcp = class_pred  + ((size_t)b * NPTS + bi1) * DCLS;
        const float* gci = class_input + ((size_t)b * NPTS + bi2) * DCLS;
        #pragma unroll
        for (int d = 0; d < DCLS; d++) {
            s1 = fmaf(gcp[d], ci[d], s1);
            s2 = fmaf(gci[d], cp[d], s2);
        }
    }

    // per-thread partial: chamfer contribution + class_loss contribution (W=1)
    float r = bd1 + bd2 - s1 - s2;

    // ---- block reduction ----
    const int lane = t & 31;
    const int wid  = t >> 5;
    float v = warpReduceSum(r);
    if (lane == 0) red[wid] = v;
    __syncthreads();
    if (wid == 0) {
        v = (lane < 16) ? red[lane] : 0.0f;
        v = warpReduceSum(v);
        if (lane == 0) red[0] = v;
    }
    __syncthreads();

    if (t == 0) {
        float S = red[0];   // chamfer_loss + class_loss

        // class-count loss
        float cn = 0.0f;
        {
            float d0 = fabsf((float)(hpred[0] - hin[0]));
            float d8 = fabsf((float)(hpred[DCLS - 1] - hin[DCLS - 1]));
            cn = d0 * 2.0f + d8 * 100.0f;
            #pragma unroll
            for (int c = 1; c < DCLS - 1; c++)
                cn += fabsf((float)(hpred[c] - hin[c]));
        }

        // KL
        float kl = 0.0f;
        const float* mub = mu      + (size_t)b * LLAT;
        const float* lvb = log_var + (size_t)b * LLAT;
        #pragma unroll
        for (int l = 0; l < LLAT; l++) {
            float m  = mub[l];
            float lv = lvb[l];
            kl += 1.0f + lv - m * m - expf(lv);
        }
        kl = -0.5f * kl;

        out[b] = 0.99f * (S + 0.001f * cn) + 0.01f * kl;
    }
}

extern "C" void kernel_launch(void* const* d_in, const int* in_sizes, int n_in,
                              void* d_out, int out_size)
{
    const float* kine_input  = (const float*)d_in[0];
    const float* class_input = (const float*)d_in[1];
    const float* kine_pred   = (const float*)d_in[2];
    const float* class_pred  = (const float*)d_in[3];
    const float* mu          = (const float*)d_in[4];
    const float* log_var     = (const float*)d_in[5];

    const int B = in_sizes[4] / LLAT;   // mu is [B, 32]

    loss_kernel<<<B, NPTS>>>(kine_input, class_input, kine_pred, class_pred,
                             mu, log_var, (float*)d_out);
}